// round 4
// baseline (speedup 1.0000x reference)
#include <cuda_runtime.h>
#include <cuda_fp16.h>
#include <cstdint>
#include <cstddef>

#define NTHREADS 256

// ---------------------------------------------------------------------------
// Shared memory layout. Float arrays first (16B aligned), then fp16 weights.
// Bank notes:
//  - P stride 66 floats: energy loop (j=tid>>1, kk=half+2i) -> banks 2j+half+2i,
//    conflict-free.
//  - Wih/Whh half2 row stride 130 (260 halfs): gates lane (r=tid>>1,p=tid&1),
//    Wih rows start on even banks, Whh (offset +4B via padw) on odd banks ->
//    p0/p1 lanes occupy disjoint banks, conflict-free.
//  - W1h half2 stride 132: Q-stage lane (kk=tid>>2,q=tid&3) reads half2 index
//    kk*132+q+4i -> banks 4kk+q distinct, conflict-free.
// ---------------------------------------------------------------------------
struct __align__(16) Smem {
    float P[128 * 66];      // [j][kk]  x-part of fcEnergy L1 (+b1), our 64-k slice
    float X[128 * 33];      // [j][e]   x e-slice (32 cols) for context
    float PE[1024];         // [src_rank][j] partial energies
    float Hc[512];          // double-buffered hidden state [2][256]
    float Ctx[256];         // gathered context
    float Qv[64];           // h-part of L1 preact for our kk slice
    float W2s[64];          // W2 slice
    float G[128];           // gate preactivations (4 gates x 32 units)
    float Bias[128];        // bih+bhh for our rows
    float Wgt[128];         // softmax weights
    float Hnew[32];         // new h slice (staging for scatter)
    float red[8];           // block reduction scratch
    float padf[8];
    __half Wih[128 * 260];  // fp16, row = gate*32+unit, 256 cols, stride 260
    __half padw[2];         // 4B -> stagger Whh banks vs Wih
    __half Whh[128 * 260];
    __half W1h[64 * 264];   // [kk][hh] W1 h-part slice, stride 264
};
// sizeof ~= 227,024 B  (< 232,448 max dynamic smem)

__device__ __forceinline__ uint32_t s2u(const void* p) {
    uint32_t a;
    asm("{ .reg .u64 t; cvta.to.shared.u64 t, %1; cvt.u32.u64 %0, t; }"
        : "=r"(a) : "l"(p));
    return a;
}
__device__ __forceinline__ void stc(uint32_t addr, uint32_t rank, float v) {
    uint32_t r;
    asm volatile("mapa.shared::cluster.u32 %0, %1, %2;" : "=r"(r) : "r"(addr), "r"(rank));
    asm volatile("st.shared::cluster.f32 [%0], %1;" :: "r"(r), "f"(v) : "memory");
}
__device__ __forceinline__ void cluster_sync() {
    asm volatile("barrier.cluster.arrive.aligned;" ::: "memory");
    asm volatile("barrier.cluster.wait.aligned;" ::: "memory");
}
__device__ __forceinline__ float tanh_fast(float x) {
    float y; asm("tanh.approx.f32 %0, %1;" : "=f"(y) : "f"(x)); return y;
}
__device__ __forceinline__ float sigm(float x) { return 1.f / (1.f + __expf(-x)); }

__device__ __forceinline__ float blockReduceMax(float v, volatile float* red, int tid) {
    #pragma unroll
    for (int o = 16; o; o >>= 1) v = fmaxf(v, __shfl_xor_sync(0xffffffffu, v, o));
    if ((tid & 31) == 0) red[tid >> 5] = v;
    __syncthreads();
    float r = red[0];
    #pragma unroll
    for (int w = 1; w < 8; ++w) r = fmaxf(r, red[w]);
    __syncthreads();
    return r;
}
__device__ __forceinline__ float blockReduceSum(float v, volatile float* red, int tid) {
    #pragma unroll
    for (int o = 16; o; o >>= 1) v += __shfl_xor_sync(0xffffffffu, v, o);
    if ((tid & 31) == 0) red[tid >> 5] = v;
    __syncthreads();
    float r = red[0];
    #pragma unroll
    for (int w = 1; w < 8; ++w) r += red[w];
    __syncthreads();
    return r;
}

__global__ void __cluster_dims__(8, 1, 1) __launch_bounds__(NTHREADS, 1)
lstm_attn_kernel(const float* __restrict__ gx, const int* __restrict__ gseq,
                 const float* __restrict__ gW1, const float* __restrict__ gb1,
                 const float* __restrict__ gW2, const float* __restrict__ gb2,
                 const float* __restrict__ gWih, const float* __restrict__ gWhh,
                 const float* __restrict__ gbih, const float* __restrict__ gbhh,
                 float* __restrict__ out)
{
    extern __shared__ char smraw[];
    Smem& sm = *reinterpret_cast<Smem*>(smraw);
    const int tid = (int)threadIdx.x;
    const int b   = (int)blockIdx.x >> 3;   // batch = cluster id
    const int c   = (int)blockIdx.x & 7;    // rank within cluster
    const int len = gseq[b];

    float* outO = out;                      // outputs  [8][128][256]
    float* outL = out + 262144;             // seq_lengths [8]
    float* outH = out + 262152;             // hidden   [1][8][256]
    float* outA = out + 264200;             // attn     [8][128][128]

    // ---------------- prologue ----------------
    sm.Hc[tid] = 0.f; sm.Hc[256 + tid] = 0.f;

    {   // zero padded output rows (d_out is poisoned)
        const int padT = 128 - len;
        for (int idx = (c << 8) + tid; idx < padT * 256; idx += 2048)
            outO[(size_t)b * 32768 + (size_t)len * 256 + idx] = 0.f;
        for (int idx = (c << 8) + tid; idx < padT * 128; idx += 2048)
            outA[(size_t)b * 16384 + (size_t)len * 128 + idx] = 0.f;
        if (c == 0 && tid == 0) outL[b] = (float)len;
    }

    // stage x[b] (fp32) into the (not yet used) Wih|Whh region, stride 259
    float* xs = reinterpret_cast<float*>(sm.Wih);
    for (int idx = tid; idx < 128 * 256; idx += NTHREADS) {
        int j = idx >> 8, e = idx & 255;
        xs[j * 259 + e] = gx[(size_t)b * 32768 + idx];
    }
    __syncthreads();

    // P[j][kk] = x[b,j,:] . W1[c*64+kk, :256] + b1   (two k-passes of 32)
    {
        float* wst = reinterpret_cast<float*>(sm.W1h);  // staging, stride 258
        const int j = tid >> 1, half = tid & 1;
        for (int pass = 0; pass < 2; ++pass) {
            for (int idx = tid; idx < 32 * 256; idx += NTHREADS) {
                int row = idx >> 8, e = idx & 255;
                wst[row * 258 + e] = gW1[(size_t)(c * 64 + pass * 32 + row) * 512 + e];
            }
            __syncthreads();
            const float* xr = xs + j * 259;
            for (int kb = 0; kb < 4; ++kb) {
                const int r0 = half + 8 * kb;   // rows r0, r0+2, r0+4, r0+6
                const float* w0 = wst + (r0 + 0) * 258;
                const float* w1 = wst + (r0 + 2) * 258;
                const float* w2 = wst + (r0 + 4) * 258;
                const float* w3 = wst + (r0 + 6) * 258;
                float a0 = 0.f, a1 = 0.f, a2 = 0.f, a3 = 0.f;
                #pragma unroll 8
                for (int e = 0; e < 256; ++e) {
                    float xv = xr[e];
                    a0 = fmaf(xv, w0[e], a0);
                    a1 = fmaf(xv, w1[e], a1);
                    a2 = fmaf(xv, w2[e], a2);
                    a3 = fmaf(xv, w3[e], a3);
                }
                const int kkb = pass * 32 + r0;
                sm.P[j * 66 + kkb    ] = a0 + gb1[c * 64 + kkb];
                sm.P[j * 66 + kkb + 2] = a1 + gb1[c * 64 + kkb + 2];
                sm.P[j * 66 + kkb + 4] = a2 + gb1[c * 64 + kkb + 4];
                sm.P[j * 66 + kkb + 6] = a3 + gb1[c * 64 + kkb + 6];
            }
            __syncthreads();
        }
    }

    // X e-slice for context (read from xs before it is overwritten)
    for (int idx = tid; idx < 128 * 32; idx += NTHREADS) {
        int j = idx >> 5, e = idx & 31;
        sm.X[j * 33 + e] = xs[j * 259 + c * 32 + e];
    }
    __syncthreads();   // all xs reads done before weight loads overwrite

    // gate weight slices -> fp16 smem. our rows: gate g, unit c*32+u
    for (int idx = tid; idx < 128 * 128; idx += NTHREADS) {
        int r = idx >> 7, i = idx & 127;
        int grow = (r >> 5) * 256 + c * 32 + (r & 31);
        float2 v = *reinterpret_cast<const float2*>(gWih + (size_t)grow * 256 + 2 * i);
        reinterpret_cast<__half2*>(sm.Wih)[r * 130 + i] = __floats2half2_rn(v.x, v.y);
    }
    for (int idx = tid; idx < 128 * 128; idx += NTHREADS) {
        int r = idx >> 7, i = idx & 127;
        int grow = (r >> 5) * 256 + c * 32 + (r & 31);
        float2 v = *reinterpret_cast<const float2*>(gWhh + (size_t)grow * 256 + 2 * i);
        reinterpret_cast<__half2*>(sm.Whh)[r * 130 + i] = __floats2half2_rn(v.x, v.y);
    }
    // W1 h-part slice -> fp16
    for (int idx = tid; idx < 64 * 128; idx += NTHREADS) {
        int kk = idx >> 7, i = idx & 127;
        float2 v = *reinterpret_cast<const float2*>(gW1 + (size_t)(c * 64 + kk) * 512 + 256 + 2 * i);
        reinterpret_cast<__half2*>(sm.W1h)[kk * 132 + i] = __floats2half2_rn(v.x, v.y);
    }
    if (tid < 64) sm.W2s[tid] = gW2[c * 64 + tid];
    if (tid < 128) {
        int g = tid >> 5, uu = tid & 31;
        sm.Bias[tid] = gbih[g * 256 + c * 32 + uu] + gbhh[g * 256 + c * 32 + uu];
    }
    __syncthreads();
    cluster_sync();

    const float b2v = gb2[0];
    const uint32_t peAddr  = s2u(sm.PE);
    const uint32_t ctxAddr = s2u(sm.Ctx);
    const uint32_t hcAddr  = s2u(sm.Hc);

    float creg = 0.f, hlast = 0.f;          // per-unit state (threads 0..31)

    // ---------------- time loop ----------------
    for (int t = 0; t < 128; ++t) {
        const bool active = (t < len);
        const float* Hcur = sm.Hc + (t & 1) * 256;

        if (active) {
            // ---- Q[kk] = h . W1h[kk,:] ----
            {
                const int kk = tid >> 2, q = tid & 3;
                const __half2* wr = reinterpret_cast<const __half2*>(sm.W1h) + kk * 132 + q;
                float acc = 0.f;
                #pragma unroll 8
                for (int i = 0; i < 32; ++i) {
                    float2 w = __half22float2(wr[4 * i]);
                    int hh = 2 * (q + 4 * i);
                    acc = fmaf(w.x, Hcur[hh], acc);
                    acc = fmaf(w.y, Hcur[hh + 1], acc);
                }
                acc += __shfl_xor_sync(0xffffffffu, acc, 1);
                acc += __shfl_xor_sync(0xffffffffu, acc, 2);
                if (q == 0) sm.Qv[kk] = acc;
            }
            __syncthreads();

            // ---- partial energies: pe[j] = sum_kk tanh(P+Q)*W2 ----
            {
                const int j = tid >> 1, half = tid & 1;
                float acc = 0.f;
                #pragma unroll
                for (int i = 0; i < 32; ++i) {
                    int kk = half + 2 * i;
                    float v = sm.P[j * 66 + kk] + sm.Qv[kk];
                    acc = fmaf(tanh_fast(v), sm.W2s[kk], acc);
                }
                acc += __shfl_xor_sync(0xffffffffu, acc, 1);
                if (half == 0) {
                    uint32_t a = peAddr + (uint32_t)((c * 128 + j) * 4);
                    #pragma unroll
                    for (int r = 0; r < 8; ++r) stc(a, r, acc);
                }
            }
            cluster_sync();   // B1: PE ready everywhere

            // ---- full energy + softmax (replicated on every rank) ----
            float ej = -1e30f;
            if (tid < 128) {
                float s = 0.f;
                #pragma unroll
                for (int r = 0; r < 8; ++r) s += sm.PE[r * 128 + tid];
                ej = (tid < len) ? tanhf(s + b2v) : -1e30f;
            }
            float m = blockReduceMax(ej, sm.red, tid);
            float ex = (tid < 128 && tid < len) ? __expf(ej - m) : 0.f;
            float ssum = blockReduceSum(ex, sm.red, tid);
            if (tid < 128) sm.Wgt[tid] = ex / ssum;
            __syncthreads();

            if (c == 0 && tid < 128)
                outA[(size_t)(b * 128 + t) * 128 + tid] = sm.Wgt[tid];

            // ---- context slice: ctx[e] = sum_j w[j]*x[j,e] ----
            {
                const int e = tid >> 3, jj = tid & 7;
                float acc = 0.f;
                #pragma unroll
                for (int mm = 0; mm < 16; ++mm) {
                    int j = jj + 8 * mm;
                    acc = fmaf(sm.Wgt[j], sm.X[j * 33 + e], acc);
                }
                acc += __shfl_xor_sync(0xffffffffu, acc, 1);
                acc += __shfl_xor_sync(0xffffffffu, acc, 2);
                acc += __shfl_xor_sync(0xffffffffu, acc, 4);
                if (jj == 0) {
                    uint32_t a = ctxAddr + (uint32_t)((c * 32 + e) * 4);
                    #pragma unroll
                    for (int r = 0; r < 8; ++r) stc(a, r, acc);
                }
            }
            cluster_sync();   // B2: Ctx ready everywhere
        }

        // ---- LSTM gates (context part skipped when inactive: ctx == 0) ----
        {
            const int r = tid >> 1, p = tid & 1;
            float acc = 0.f;
            if (p == 1) {
                const __half2* wv = reinterpret_cast<const __half2*>(sm.Whh) + r * 130;
                #pragma unroll 16
                for (int i = 0; i < 128; ++i) {
                    float2 w = __half22float2(wv[i]);
                    float2 v = *reinterpret_cast<const float2*>(Hcur + 2 * i);
                    acc = fmaf(w.x, v.x, acc);
                    acc = fmaf(w.y, v.y, acc);
                }
            } else if (active) {
                const __half2* wv = reinterpret_cast<const __half2*>(sm.Wih) + r * 130;
                #pragma unroll 16
                for (int i = 0; i < 128; ++i) {
                    float2 w = __half22float2(wv[i]);
                    float2 v = *reinterpret_cast<const float2*>(sm.Ctx + 2 * i);
                    acc = fmaf(w.x, v.x, acc);
                    acc = fmaf(w.y, v.y, acc);
                }
            }
            acc += __shfl_xor_sync(0xffffffffu, acc, 1);
            if (p == 0) sm.G[r] = acc + sm.Bias[r];
        }
        __syncthreads();

        // ---- state update (32 units per CTA) ----
        if (tid < 32) {
            float gi = sm.G[tid],      gf = sm.G[32 + tid];
            float gg = sm.G[64 + tid], go = sm.G[96 + tid];
            creg = sigm(gf) * creg + sigm(gi) * tanhf(gg);
            float hn = sigm(go) * tanhf(creg);
            if (t == len - 1) hlast = hn;
            if (active)
                outO[(size_t)(b * 128 + t) * 256 + (c * 32 + tid)] = hn;
            sm.Hnew[tid] = hn;
        }
        __syncthreads();

        // ---- all-gather h into the NEXT Hc buffer ----
        {
            const int rk = tid >> 5, uu = tid & 31;
            uint32_t a = hcAddr + (uint32_t)(((((t + 1) & 1) * 256) + c * 32 + uu) * 4);
            stc(a, rk, sm.Hnew[uu]);
        }
        cluster_sync();   // B3: h ready for step t+1
    }

    if (tid < 32)
        outH[(size_t)b * 256 + c * 32 + tid] = hlast;
}

extern "C" void kernel_launch(void* const* d_in, const int* in_sizes, int n_in,
                              void* d_out, int out_size) {
    (void)in_sizes; (void)n_in; (void)out_size;
    const float* x    = (const float*)d_in[0];
    const int*   seq  = (const int*)d_in[1];
    const float* W1   = (const float*)d_in[2];
    const float* b1   = (const float*)d_in[3];
    const float* W2   = (const float*)d_in[4];
    const float* b2   = (const float*)d_in[5];
    const float* Wih  = (const float*)d_in[6];
    const float* Whh  = (const float*)d_in[7];
    const float* bih  = (const float*)d_in[8];
    const float* bhh  = (const float*)d_in[9];
    float* out = (float*)d_out;

    cudaFuncSetAttribute(lstm_attn_kernel,
                         cudaFuncAttributeMaxDynamicSharedMemorySize,
                         (int)sizeof(Smem));
    lstm_attn_kernel<<<64, NTHREADS, sizeof(Smem)>>>(
        x, seq, W1, b1, W2, b2, Wih, Whh, bih, bhh, out);
}

// round 5
// speedup vs baseline: 1.1211x; 1.1211x over previous
#include <cuda_runtime.h>
#include <cuda_fp16.h>
#include <cstdint>
#include <cstddef>

#define NTHREADS 256

// ---------------------------------------------------------------------------
// Shared memory. Gate weights now live in REGISTERS (128 half2/thread); smem
// holds the time-invariant attention precompute P, activations, and exchange
// buffers. `stage` is prologue-only scratch (x fp32 staging).
// ---------------------------------------------------------------------------
struct __align__(16) Smem {
    float P[128 * 66];      // [j][kk] x-part of fcEnergy L1 (+b1), our 64-k slice
    float X[128 * 33];      // [j][e]  x e-slice (32 cols) for context
    float PE[1024];         // [src_rank][j] partial energies
    float Hc[512];          // double-buffered hidden state [2][256]
    float Ctx[256];         // gathered context
    float Qv[64];           // h-part of L1 preact for our kk slice
    float W2s[64];          // W2 slice
    float G[128];           // gate preactivations
    float Bias[128];        // bih+bhh for our rows
    float Wgt[128];         // softmax weights (written redundantly per warp)
    float Hnew[32];         // new h slice (scatter staging)
    float padf[8];
    __half W1h[64 * 264];   // [kk][hh] W1 h-part slice (also fp32 W1 staging in prologue)
    float stage[128 * 259]; // prologue x staging
};
// total = 226,464 B  (< 232,448 max dynamic smem)

__device__ __forceinline__ uint32_t s2u(const void* p) {
    uint32_t a;
    asm("{ .reg .u64 t; cvta.to.shared.u64 t, %1; cvt.u32.u64 %0, t; }"
        : "=r"(a) : "l"(p));
    return a;
}
__device__ __forceinline__ void stc(uint32_t addr, uint32_t rank, float v) {
    uint32_t r;
    asm volatile("mapa.shared::cluster.u32 %0, %1, %2;" : "=r"(r) : "r"(addr), "r"(rank));
    asm volatile("st.shared::cluster.f32 [%0], %1;" :: "r"(r), "f"(v) : "memory");
}
__device__ __forceinline__ void cluster_sync() {
    asm volatile("barrier.cluster.arrive.aligned;" ::: "memory");
    asm volatile("barrier.cluster.wait.aligned;" ::: "memory");
}
__device__ __forceinline__ float tanh_fast(float x) {
    float y; asm("tanh.approx.f32 %0, %1;" : "=f"(y) : "f"(x)); return y;
}
__device__ __forceinline__ float sigm(float x) { return 1.f / (1.f + __expf(-x)); }

__global__ void __cluster_dims__(8, 1, 1) __launch_bounds__(NTHREADS, 1)
lstm_attn_kernel(const float* __restrict__ gx, const int* __restrict__ gseq,
                 const float* __restrict__ gW1, const float* __restrict__ gb1,
                 const float* __restrict__ gW2, const float* __restrict__ gb2,
                 const float* __restrict__ gWih, const float* __restrict__ gWhh,
                 const float* __restrict__ gbih, const float* __restrict__ gbhh,
                 float* __restrict__ out)
{
    extern __shared__ char smraw[];
    Smem& sm = *reinterpret_cast<Smem*>(smraw);
    const int tid = (int)threadIdx.x;
    const int b   = (int)blockIdx.x >> 3;   // batch = cluster id
    const int c   = (int)blockIdx.x & 7;    // rank within cluster
    const int len = gseq[b];

    float* outO = out;                      // outputs  [8][128][256]
    float* outL = out + 262144;             // seq_lengths [8]
    float* outH = out + 262152;             // hidden   [1][8][256]
    float* outA = out + 264200;             // attn     [8][128][128]

    // ---------------- prologue ----------------
    sm.Hc[tid] = 0.f; sm.Hc[256 + tid] = 0.f;

    {   // zero padded output rows (d_out is poisoned)
        const int padT = 128 - len;
        for (int idx = (c << 8) + tid; idx < padT * 256; idx += 2048)
            outO[(size_t)b * 32768 + (size_t)len * 256 + idx] = 0.f;
        for (int idx = (c << 8) + tid; idx < padT * 128; idx += 2048)
            outA[(size_t)b * 16384 + (size_t)len * 128 + idx] = 0.f;
        if (c == 0 && tid == 0) outL[b] = (float)len;
    }

    // stage x[b] (fp32), stride 259
    float* xs = sm.stage;
    for (int idx = tid; idx < 128 * 256; idx += NTHREADS) {
        int j = idx >> 8, e = idx & 255;
        xs[j * 259 + e] = gx[(size_t)b * 32768 + idx];
    }
    __syncthreads();

    // P[j][kk] = x[b,j,:] . W1[c*64+kk, :256] + b1   (two k-passes of 32)
    {
        float* wst = reinterpret_cast<float*>(sm.W1h);  // staging, stride 258
        const int j = tid >> 1, half = tid & 1;
        for (int pass = 0; pass < 2; ++pass) {
            for (int idx = tid; idx < 32 * 256; idx += NTHREADS) {
                int row = idx >> 8, e = idx & 255;
                wst[row * 258 + e] = gW1[(size_t)(c * 64 + pass * 32 + row) * 512 + e];
            }
            __syncthreads();
            const float* xr = xs + j * 259;
            for (int kb = 0; kb < 4; ++kb) {
                const int r0 = half + 8 * kb;
                const float* w0 = wst + (r0 + 0) * 258;
                const float* w1 = wst + (r0 + 2) * 258;
                const float* w2 = wst + (r0 + 4) * 258;
                const float* w3 = wst + (r0 + 6) * 258;
                float a0 = 0.f, a1 = 0.f, a2 = 0.f, a3 = 0.f;
                #pragma unroll 8
                for (int e = 0; e < 256; ++e) {
                    float xv = xr[e];
                    a0 = fmaf(xv, w0[e], a0);
                    a1 = fmaf(xv, w1[e], a1);
                    a2 = fmaf(xv, w2[e], a2);
                    a3 = fmaf(xv, w3[e], a3);
                }
                const int kkb = pass * 32 + r0;
                sm.P[j * 66 + kkb    ] = a0 + gb1[c * 64 + kkb];
                sm.P[j * 66 + kkb + 2] = a1 + gb1[c * 64 + kkb + 2];
                sm.P[j * 66 + kkb + 4] = a2 + gb1[c * 64 + kkb + 4];
                sm.P[j * 66 + kkb + 6] = a3 + gb1[c * 64 + kkb + 6];
            }
            __syncthreads();
        }
    }

    // X e-slice for context (from xs before anything overwrites W1h staging)
    for (int idx = tid; idx < 128 * 32; idx += NTHREADS) {
        int j = idx >> 5, e = idx & 31;
        sm.X[j * 33 + e] = xs[j * 259 + c * 32 + e];
    }
    __syncthreads();

    // W1 h-part slice -> fp16 smem (overwrites its own fp32 staging; synced above)
    for (int idx = tid; idx < 64 * 128; idx += NTHREADS) {
        int kk = idx >> 7, i = idx & 127;
        float2 v = *reinterpret_cast<const float2*>(gW1 + (size_t)(c * 64 + kk) * 512 + 256 + 2 * i);
        reinterpret_cast<__half2*>(sm.W1h)[kk * 132 + i] = __floats2half2_rn(v.x, v.y);
    }
    if (tid < 64) sm.W2s[tid] = gW2[c * 64 + tid];
    if (tid < 128) {
        int g = tid >> 5, uu = tid & 31;
        sm.Bias[tid] = gbih[g * 256 + c * 32 + uu] + gbhh[g * 256 + c * 32 + uu];
    }

    // ---- gate weights into REGISTERS: row r = tid>>1, column half p = tid&1 ----
    const int r_row = tid >> 1, p = tid & 1;
    uint32_t wih_r[64], whh_r[64];
    {
        const int grow = (r_row >> 5) * 256 + c * 32 + (r_row & 31);
        const float* bih_ = gWih + (size_t)grow * 256 + (p << 7);
        const float* bhh_ = gWhh + (size_t)grow * 256 + (p << 7);
        #pragma unroll
        for (int i = 0; i < 64; ++i) {
            float2 v = *reinterpret_cast<const float2*>(bih_ + 2 * i);
            __half2 h2 = __floats2half2_rn(v.x, v.y);
            wih_r[i] = *reinterpret_cast<uint32_t*>(&h2);
        }
        #pragma unroll
        for (int i = 0; i < 64; ++i) {
            float2 v = *reinterpret_cast<const float2*>(bhh_ + 2 * i);
            __half2 h2 = __floats2half2_rn(v.x, v.y);
            whh_r[i] = *reinterpret_cast<uint32_t*>(&h2);
        }
    }
    __syncthreads();
    cluster_sync();

    const float b2v = gb2[0];
    const uint32_t peAddr  = s2u(sm.PE);
    const uint32_t ctxAddr = s2u(sm.Ctx);
    const uint32_t hcAddr  = s2u(sm.Hc);
    const int lane = tid & 31;

    float creg = 0.f, hlast = 0.f;          // per-unit state (threads 0..31)

    // ---------------- time loop ----------------
    for (int t = 0; t < 128; ++t) {
        const bool active = (t < len);
        const float* Hcur = sm.Hc + (t & 1) * 256;

        if (active) {
            // ---- Q[kk] = h . W1h[kk,:] ----
            {
                const int kk = tid >> 2, q = tid & 3;
                const __half2* wr = reinterpret_cast<const __half2*>(sm.W1h) + kk * 132 + q;
                float acc = 0.f;
                #pragma unroll 8
                for (int i = 0; i < 32; ++i) {
                    float2 w = __half22float2(wr[4 * i]);
                    int hh = 2 * (q + 4 * i);
                    acc = fmaf(w.x, Hcur[hh], acc);
                    acc = fmaf(w.y, Hcur[hh + 1], acc);
                }
                acc += __shfl_xor_sync(0xffffffffu, acc, 1);
                acc += __shfl_xor_sync(0xffffffffu, acc, 2);
                if (q == 0) sm.Qv[kk] = acc;
            }
            __syncthreads();

            // ---- partial energies: pe[j] = sum_kk tanh(P+Q)*W2 ----
            {
                const int j = tid >> 1, half = tid & 1;
                float acc = 0.f;
                #pragma unroll
                for (int i = 0; i < 32; ++i) {
                    int kk = half + 2 * i;
                    float v = sm.P[j * 66 + kk] + sm.Qv[kk];
                    acc = fmaf(tanh_fast(v), sm.W2s[kk], acc);
                }
                acc += __shfl_xor_sync(0xffffffffu, acc, 1);
                if (half == 0) {
                    uint32_t a = peAddr + (uint32_t)((c * 128 + j) * 4);
                    #pragma unroll
                    for (int rr = 0; rr < 8; ++rr) stc(a, rr, acc);
                }
            }
            cluster_sync();   // B1: PE ready everywhere

            // ---- warp-local softmax (each warp computes all 128 j's) ----
            {
                float e[4];
                #pragma unroll
                for (int q = 0; q < 4; ++q) {
                    const int j = lane + 32 * q;
                    float s = 0.f;
                    #pragma unroll
                    for (int rr = 0; rr < 8; ++rr) s += sm.PE[rr * 128 + j];
                    e[q] = (j < len) ? tanhf(s + b2v) : -1e30f;
                }
                float m = fmaxf(fmaxf(e[0], e[1]), fmaxf(e[2], e[3]));
                #pragma unroll
                for (int o = 16; o; o >>= 1) m = fmaxf(m, __shfl_xor_sync(0xffffffffu, m, o));
                float w[4], ssum = 0.f;
                #pragma unroll
                for (int q = 0; q < 4; ++q) { w[q] = __expf(e[q] - m); ssum += w[q]; }
                #pragma unroll
                for (int o = 16; o; o >>= 1) ssum += __shfl_xor_sync(0xffffffffu, ssum, o);
                const float inv = 1.f / ssum;
                #pragma unroll
                for (int q = 0; q < 4; ++q) {
                    w[q] *= inv;
                    sm.Wgt[lane + 32 * q] = w[q];   // identical values from all warps
                }
                if (c == 0 && tid < 32) {           // warp 0 of rank 0 covers all j
                    float* row = outA + (size_t)(b * 128 + t) * 128;
                    #pragma unroll
                    for (int q = 0; q < 4; ++q) row[lane + 32 * q] = w[q];
                }
            }
            __syncwarp();

            // ---- context slice: warp w owns e in [4w, 4w+4) ----
            {
                const int e = ((tid >> 5) << 2) + (lane >> 3);
                const int jj = lane & 7;
                float acc = 0.f;
                #pragma unroll
                for (int mm = 0; mm < 16; ++mm) {
                    int j = jj + 8 * mm;
                    acc = fmaf(sm.Wgt[j], sm.X[j * 33 + e], acc);
                }
                acc += __shfl_xor_sync(0xffffffffu, acc, 1);
                acc += __shfl_xor_sync(0xffffffffu, acc, 2);
                acc += __shfl_xor_sync(0xffffffffu, acc, 4);
                if (jj == 0) {
                    uint32_t a = ctxAddr + (uint32_t)((c * 32 + e) * 4);
                    #pragma unroll
                    for (int rr = 0; rr < 8; ++rr) stc(a, rr, acc);
                }
            }
            cluster_sync();   // B2: Ctx ready everywhere
        }

        // ---- LSTM gates: weights in registers, activations broadcast from smem ----
        {
            float a0 = 0.f, a1 = 0.f;
            const float4* h4 = reinterpret_cast<const float4*>(Hcur + (p << 7));
            #pragma unroll
            for (int i = 0; i < 32; ++i) {
                float4 v = h4[i];
                float2 w0 = __half22float2(*reinterpret_cast<const __half2*>(&whh_r[2 * i]));
                float2 w1 = __half22float2(*reinterpret_cast<const __half2*>(&whh_r[2 * i + 1]));
                a0 = fmaf(w0.x, v.x, a0); a1 = fmaf(w0.y, v.y, a1);
                a0 = fmaf(w1.x, v.z, a0); a1 = fmaf(w1.y, v.w, a1);
            }
            if (active) {
                const float4* c4 = reinterpret_cast<const float4*>(sm.Ctx + (p << 7));
                #pragma unroll
                for (int i = 0; i < 32; ++i) {
                    float4 v = c4[i];
                    float2 w0 = __half22float2(*reinterpret_cast<const __half2*>(&wih_r[2 * i]));
                    float2 w1 = __half22float2(*reinterpret_cast<const __half2*>(&wih_r[2 * i + 1]));
                    a0 = fmaf(w0.x, v.x, a0); a1 = fmaf(w0.y, v.y, a1);
                    a0 = fmaf(w1.x, v.z, a0); a1 = fmaf(w1.y, v.w, a1);
                }
            }
            float acc = a0 + a1;
            acc += __shfl_xor_sync(0xffffffffu, acc, 1);
            if (p == 0) sm.G[r_row] = acc + sm.Bias[r_row];
        }
        __syncthreads();

        // ---- state update (32 units per CTA) ----
        if (tid < 32) {
            float gi = sm.G[tid],      gf = sm.G[32 + tid];
            float gg = sm.G[64 + tid], go = sm.G[96 + tid];
            creg = sigm(gf) * creg + sigm(gi) * tanhf(gg);
            float hn = sigm(go) * tanhf(creg);
            if (t == len - 1) hlast = hn;
            if (active)
                outO[(size_t)(b * 128 + t) * 256 + (c * 32 + tid)] = hn;
            sm.Hnew[tid] = hn;
        }
        __syncthreads();

        // ---- all-gather h into the NEXT Hc buffer ----
        {
            const int rk = tid >> 5, uu = tid & 31;
            uint32_t a = hcAddr + (uint32_t)(((((t + 1) & 1) * 256) + c * 32 + uu) * 4);
            stc(a, rk, sm.Hnew[uu]);
        }
        cluster_sync();   // B3: h ready for step t+1
    }

    if (tid < 32)
        outH[(size_t)b * 256 + c * 32 + tid] = hlast;
}

extern "C" void kernel_launch(void* const* d_in, const int* in_sizes, int n_in,
                              void* d_out, int out_size) {
    (void)in_sizes; (void)n_in; (void)out_size;
    const float* x    = (const float*)d_in[0];
    const int*   seq  = (const int*)d_in[1];
    const float* W1   = (const float*)d_in[2];
    const float* b1   = (const float*)d_in[3];
    const float* W2   = (const float*)d_in[4];
    const float* b2   = (const float*)d_in[5];
    const float* Wih  = (const float*)d_in[6];
    const float* Whh  = (const float*)d_in[7];
    const float* bih  = (const float*)d_in[8];
    const float* bhh  = (const float*)d_in[9];
    float* out = (float*)d_out;

    cudaFuncSetAttribute(lstm_attn_kernel,
                         cudaFuncAttributeMaxDynamicSharedMemorySize,
                         (int)sizeof(Smem));
    lstm_attn_kernel<<<64, NTHREADS, sizeof(Smem)>>>(
        x, seq, W1, b1, W2, b2, Wih, Whh, bih, bhh, out);
}

// round 6
// speedup vs baseline: 1.1289x; 1.0070x over previous
#include <cuda_runtime.h>
#include <cuda_fp16.h>
#include <cstdint>
#include <cstddef>

#define NTHREADS 256

// ---------------------------------------------------------------------------
// Shared memory. Gate weights now live in REGISTERS (128 half2/thread); smem
// holds the time-invariant attention precompute P, activations, and exchange
// buffers. `stage` is prologue-only scratch (x fp32 staging).
// ---------------------------------------------------------------------------
struct __align__(16) Smem {
    float P[128 * 66];      // [j][kk] x-part of fcEnergy L1 (+b1), our 64-k slice
    float X[128 * 33];      // [j][e]  x e-slice (32 cols) for context
    float PE[1024];         // [src_rank][j] partial energies
    float Hc[512];          // double-buffered hidden state [2][256]
    float Ctx[256];         // gathered context
    float Qv[64];           // h-part of L1 preact for our kk slice
    float W2s[64];          // W2 slice
    float G[128];           // gate preactivations
    float Bias[128];        // bih+bhh for our rows
    float Wgt[128];         // softmax weights (written redundantly per warp)
    float Hnew[32];         // new h slice (scatter staging)
    float padf[8];
    __half W1h[64 * 264];   // [kk][hh] W1 h-part slice (also fp32 W1 staging in prologue)
    float stage[128 * 259]; // prologue x staging
};
// total = 226,464 B  (< 232,448 max dynamic smem)

__device__ __forceinline__ uint32_t s2u(const void* p) {
    uint32_t a;
    asm("{ .reg .u64 t; cvta.to.shared.u64 t, %1; cvt.u32.u64 %0, t; }"
        : "=r"(a) : "l"(p));
    return a;
}
__device__ __forceinline__ void stc(uint32_t addr, uint32_t rank, float v) {
    uint32_t r;
    asm volatile("mapa.shared::cluster.u32 %0, %1, %2;" : "=r"(r) : "r"(addr), "r"(rank));
    asm volatile("st.shared::cluster.f32 [%0], %1;" :: "r"(r), "f"(v) : "memory");
}
__device__ __forceinline__ void cluster_sync() {
    asm volatile("barrier.cluster.arrive.aligned;" ::: "memory");
    asm volatile("barrier.cluster.wait.aligned;" ::: "memory");
}
__device__ __forceinline__ float tanh_fast(float x) {
    float y; asm("tanh.approx.f32 %0, %1;" : "=f"(y) : "f"(x)); return y;
}
__device__ __forceinline__ float sigm(float x) { return 1.f / (1.f + __expf(-x)); }

__global__ void __cluster_dims__(8, 1, 1) __launch_bounds__(NTHREADS, 1)
lstm_attn_kernel(const float* __restrict__ gx, const int* __restrict__ gseq,
                 const float* __restrict__ gW1, const float* __restrict__ gb1,
                 const float* __restrict__ gW2, const float* __restrict__ gb2,
                 const float* __restrict__ gWih, const float* __restrict__ gWhh,
                 const float* __restrict__ gbih, const float* __restrict__ gbhh,
                 float* __restrict__ out)
{
    extern __shared__ char smraw[];
    Smem& sm = *reinterpret_cast<Smem*>(smraw);
    const int tid = (int)threadIdx.x;
    const int b   = (int)blockIdx.x >> 3;   // batch = cluster id
    const int c   = (int)blockIdx.x & 7;    // rank within cluster
    const int len = gseq[b];

    float* outO = out;                      // outputs  [8][128][256]
    float* outL = out + 262144;             // seq_lengths [8]
    float* outH = out + 262152;             // hidden   [1][8][256]
    float* outA = out + 264200;             // attn     [8][128][128]

    // ---------------- prologue ----------------
    sm.Hc[tid] = 0.f; sm.Hc[256 + tid] = 0.f;

    {   // zero padded output rows (d_out is poisoned)
        const int padT = 128 - len;
        for (int idx = (c << 8) + tid; idx < padT * 256; idx += 2048)
            outO[(size_t)b * 32768 + (size_t)len * 256 + idx] = 0.f;
        for (int idx = (c << 8) + tid; idx < padT * 128; idx += 2048)
            outA[(size_t)b * 16384 + (size_t)len * 128 + idx] = 0.f;
        if (c == 0 && tid == 0) outL[b] = (float)len;
    }

    // stage x[b] (fp32), stride 259
    float* xs = sm.stage;
    for (int idx = tid; idx < 128 * 256; idx += NTHREADS) {
        int j = idx >> 8, e = idx & 255;
        xs[j * 259 + e] = gx[(size_t)b * 32768 + idx];
    }
    __syncthreads();

    // P[j][kk] = x[b,j,:] . W1[c*64+kk, :256] + b1   (two k-passes of 32)
    {
        float* wst = reinterpret_cast<float*>(sm.W1h);  // staging, stride 258
        const int j = tid >> 1, half = tid & 1;
        for (int pass = 0; pass < 2; ++pass) {
            for (int idx = tid; idx < 32 * 256; idx += NTHREADS) {
                int row = idx >> 8, e = idx & 255;
                wst[row * 258 + e] = gW1[(size_t)(c * 64 + pass * 32 + row) * 512 + e];
            }
            __syncthreads();
            const float* xr = xs + j * 259;
            for (int kb = 0; kb < 4; ++kb) {
                const int r0 = half + 8 * kb;
                const float* w0 = wst + (r0 + 0) * 258;
                const float* w1 = wst + (r0 + 2) * 258;
                const float* w2 = wst + (r0 + 4) * 258;
                const float* w3 = wst + (r0 + 6) * 258;
                float a0 = 0.f, a1 = 0.f, a2 = 0.f, a3 = 0.f;
                #pragma unroll 8
                for (int e = 0; e < 256; ++e) {
                    float xv = xr[e];
                    a0 = fmaf(xv, w0[e], a0);
                    a1 = fmaf(xv, w1[e], a1);
                    a2 = fmaf(xv, w2[e], a2);
                    a3 = fmaf(xv, w3[e], a3);
                }
                const int kkb = pass * 32 + r0;
                sm.P[j * 66 + kkb    ] = a0 + gb1[c * 64 + kkb];
                sm.P[j * 66 + kkb + 2] = a1 + gb1[c * 64 + kkb + 2];
                sm.P[j * 66 + kkb + 4] = a2 + gb1[c * 64 + kkb + 4];
                sm.P[j * 66 + kkb + 6] = a3 + gb1[c * 64 + kkb + 6];
            }
            __syncthreads();
        }
    }

    // X e-slice for context (from xs before anything overwrites W1h staging)
    for (int idx = tid; idx < 128 * 32; idx += NTHREADS) {
        int j = idx >> 5, e = idx & 31;
        sm.X[j * 33 + e] = xs[j * 259 + c * 32 + e];
    }
    __syncthreads();

    // W1 h-part slice -> fp16 smem (overwrites its own fp32 staging; synced above)
    for (int idx = tid; idx < 64 * 128; idx += NTHREADS) {
        int kk = idx >> 7, i = idx & 127;
        float2 v = *reinterpret_cast<const float2*>(gW1 + (size_t)(c * 64 + kk) * 512 + 256 + 2 * i);
        reinterpret_cast<__half2*>(sm.W1h)[kk * 132 + i] = __floats2half2_rn(v.x, v.y);
    }
    if (tid < 64) sm.W2s[tid] = gW2[c * 64 + tid];
    if (tid < 128) {
        int g = tid >> 5, uu = tid & 31;
        sm.Bias[tid] = gbih[g * 256 + c * 32 + uu] + gbhh[g * 256 + c * 32 + uu];
    }

    // ---- gate weights into REGISTERS: row r = tid>>1, column half p = tid&1 ----
    const int r_row = tid >> 1, p = tid & 1;
    uint32_t wih_r[64], whh_r[64];
    {
        const int grow = (r_row >> 5) * 256 + c * 32 + (r_row & 31);
        const float* bih_ = gWih + (size_t)grow * 256 + (p << 7);
        const float* bhh_ = gWhh + (size_t)grow * 256 + (p << 7);
        #pragma unroll
        for (int i = 0; i < 64; ++i) {
            float2 v = *reinterpret_cast<const float2*>(bih_ + 2 * i);
            __half2 h2 = __floats2half2_rn(v.x, v.y);
            wih_r[i] = *reinterpret_cast<uint32_t*>(&h2);
        }
        #pragma unroll
        for (int i = 0; i < 64; ++i) {
            float2 v = *reinterpret_cast<const float2*>(bhh_ + 2 * i);
            __half2 h2 = __floats2half2_rn(v.x, v.y);
            whh_r[i] = *reinterpret_cast<uint32_t*>(&h2);
        }
    }
    __syncthreads();
    cluster_sync();

    const float b2v = gb2[0];
    const uint32_t peAddr  = s2u(sm.PE);
    const uint32_t ctxAddr = s2u(sm.Ctx);
    const uint32_t hcAddr  = s2u(sm.Hc);
    const int lane = tid & 31;

    float creg = 0.f, hlast = 0.f;          // per-unit state (threads 0..31)

    // ---------------- time loop ----------------
    for (int t = 0; t < 128; ++t) {
        const bool active = (t < len);
        const float* Hcur = sm.Hc + (t & 1) * 256;

        if (active) {
            // ---- Q[kk] = h . W1h[kk,:] ----
            {
                const int kk = tid >> 2, q = tid & 3;
                const __half2* wr = reinterpret_cast<const __half2*>(sm.W1h) + kk * 132 + q;
                float acc = 0.f;
                #pragma unroll 8
                for (int i = 0; i < 32; ++i) {
                    float2 w = __half22float2(wr[4 * i]);
                    int hh = 2 * (q + 4 * i);
                    acc = fmaf(w.x, Hcur[hh], acc);
                    acc = fmaf(w.y, Hcur[hh + 1], acc);
                }
                acc += __shfl_xor_sync(0xffffffffu, acc, 1);
                acc += __shfl_xor_sync(0xffffffffu, acc, 2);
                if (q == 0) sm.Qv[kk] = acc;
            }
            __syncthreads();

            // ---- partial energies: pe[j] = sum_kk tanh(P+Q)*W2 ----
            {
                const int j = tid >> 1, half = tid & 1;
                float acc = 0.f;
                #pragma unroll
                for (int i = 0; i < 32; ++i) {
                    int kk = half + 2 * i;
                    float v = sm.P[j * 66 + kk] + sm.Qv[kk];
                    acc = fmaf(tanh_fast(v), sm.W2s[kk], acc);
                }
                acc += __shfl_xor_sync(0xffffffffu, acc, 1);
                if (half == 0) {
                    uint32_t a = peAddr + (uint32_t)((c * 128 + j) * 4);
                    #pragma unroll
                    for (int rr = 0; rr < 8; ++rr) stc(a, rr, acc);
                }
            }
            cluster_sync();   // B1: PE ready everywhere

            // ---- warp-local softmax (each warp computes all 128 j's) ----
            {
                float e[4];
                #pragma unroll
                for (int q = 0; q < 4; ++q) {
                    const int j = lane + 32 * q;
                    float s = 0.f;
                    #pragma unroll
                    for (int rr = 0; rr < 8; ++rr) s += sm.PE[rr * 128 + j];
                    e[q] = (j < len) ? tanhf(s + b2v) : -1e30f;
                }
                float m = fmaxf(fmaxf(e[0], e[1]), fmaxf(e[2], e[3]));
                #pragma unroll
                for (int o = 16; o; o >>= 1) m = fmaxf(m, __shfl_xor_sync(0xffffffffu, m, o));
                float w[4], ssum = 0.f;
                #pragma unroll
                for (int q = 0; q < 4; ++q) { w[q] = __expf(e[q] - m); ssum += w[q]; }
                #pragma unroll
                for (int o = 16; o; o >>= 1) ssum += __shfl_xor_sync(0xffffffffu, ssum, o);
                const float inv = 1.f / ssum;
                #pragma unroll
                for (int q = 0; q < 4; ++q) {
                    w[q] *= inv;
                    sm.Wgt[lane + 32 * q] = w[q];   // identical values from all warps
                }
                if (c == 0 && tid < 32) {           // warp 0 of rank 0 covers all j
                    float* row = outA + (size_t)(b * 128 + t) * 128;
                    #pragma unroll
                    for (int q = 0; q < 4; ++q) row[lane + 32 * q] = w[q];
                }
            }
            __syncwarp();

            // ---- context slice: warp w owns e in [4w, 4w+4) ----
            {
                const int e = ((tid >> 5) << 2) + (lane >> 3);
                const int jj = lane & 7;
                float acc = 0.f;
                #pragma unroll
                for (int mm = 0; mm < 16; ++mm) {
                    int j = jj + 8 * mm;
                    acc = fmaf(sm.Wgt[j], sm.X[j * 33 + e], acc);
                }
                acc += __shfl_xor_sync(0xffffffffu, acc, 1);
                acc += __shfl_xor_sync(0xffffffffu, acc, 2);
                acc += __shfl_xor_sync(0xffffffffu, acc, 4);
                if (jj == 0) {
                    uint32_t a = ctxAddr + (uint32_t)((c * 32 + e) * 4);
                    #pragma unroll
                    for (int rr = 0; rr < 8; ++rr) stc(a, rr, acc);
                }
            }
            cluster_sync();   // B2: Ctx ready everywhere
        }

        // ---- LSTM gates: weights in registers, activations broadcast from smem ----
        {
            float a0 = 0.f, a1 = 0.f;
            const float4* h4 = reinterpret_cast<const float4*>(Hcur + (p << 7));
            #pragma unroll
            for (int i = 0; i < 32; ++i) {
                float4 v = h4[i];
                float2 w0 = __half22float2(*reinterpret_cast<const __half2*>(&whh_r[2 * i]));
                float2 w1 = __half22float2(*reinterpret_cast<const __half2*>(&whh_r[2 * i + 1]));
                a0 = fmaf(w0.x, v.x, a0); a1 = fmaf(w0.y, v.y, a1);
                a0 = fmaf(w1.x, v.z, a0); a1 = fmaf(w1.y, v.w, a1);
            }
            if (active) {
                const float4* c4 = reinterpret_cast<const float4*>(sm.Ctx + (p << 7));
                #pragma unroll
                for (int i = 0; i < 32; ++i) {
                    float4 v = c4[i];
                    float2 w0 = __half22float2(*reinterpret_cast<const __half2*>(&wih_r[2 * i]));
                    float2 w1 = __half22float2(*reinterpret_cast<const __half2*>(&wih_r[2 * i + 1]));
                    a0 = fmaf(w0.x, v.x, a0); a1 = fmaf(w0.y, v.y, a1);
                    a0 = fmaf(w1.x, v.z, a0); a1 = fmaf(w1.y, v.w, a1);
                }
            }
            float acc = a0 + a1;
            acc += __shfl_xor_sync(0xffffffffu, acc, 1);
            if (p == 0) sm.G[r_row] = acc + sm.Bias[r_row];
        }
        __syncthreads();

        // ---- state update (32 units per CTA) ----
        if (tid < 32) {
            float gi = sm.G[tid],      gf = sm.G[32 + tid];
            float gg = sm.G[64 + tid], go = sm.G[96 + tid];
            creg = sigm(gf) * creg + sigm(gi) * tanhf(gg);
            float hn = sigm(go) * tanhf(creg);
            if (t == len - 1) hlast = hn;
            if (active)
                outO[(size_t)(b * 128 + t) * 256 + (c * 32 + tid)] = hn;
            sm.Hnew[tid] = hn;
        }
        __syncthreads();

        // ---- all-gather h into the NEXT Hc buffer ----
        {
            const int rk = tid >> 5, uu = tid & 31;
            uint32_t a = hcAddr + (uint32_t)(((((t + 1) & 1) * 256) + c * 32 + uu) * 4);
            stc(a, rk, sm.Hnew[uu]);
        }
        cluster_sync();   // B3: h ready for step t+1
    }

    if (tid < 32)
        outH[(size_t)b * 256 + c * 32 + tid] = hlast;
}

extern "C" void kernel_launch(void* const* d_in, const int* in_sizes, int n_in,
                              void* d_out, int out_size) {
    (void)in_sizes; (void)n_in; (void)out_size;
    const float* x    = (const float*)d_in[0];
    const int*   seq  = (const int*)d_in[1];
    const float* W1   = (const float*)d_in[2];
    const float* b1   = (const float*)d_in[3];
    const float* W2   = (const float*)d_in[4];
    const float* b2   = (const float*)d_in[5];
    const float* Wih  = (const float*)d_in[6];
    const float* Whh  = (const float*)d_in[7];
    const float* bih  = (const float*)d_in[8];
    const float* bhh  = (const float*)d_in[9];
    float* out = (float*)d_out;

    cudaFuncSetAttribute(lstm_attn_kernel,
                         cudaFuncAttributeMaxDynamicSharedMemorySize,
                         (int)sizeof(Smem));
    lstm_attn_kernel<<<64, NTHREADS, sizeof(Smem)>>>(
        x, seq, W1, b1, W2, b2, Wih, Whh, bih, bhh, out);
}